// round 12
// baseline (speedup 1.0000x reference)
#include <cuda_runtime.h>
#include <cstdint>

#define IMGS 32
#define H 768
#define W 768
#define NPIX (H*W)
#define TW 96            // output tile width
#define TH 64            // output tile height
#define WARPS 16
#define THREADS (WARPS*32)
#define ROWS_PW 6        // region rows per warp
#define EPS 1e-6f
#define RED_CTAS 64
#define RED_THREADS 256

__device__ float g_skel[2][IMGS * NPIX];
__device__ float g_acc[2][IMGS * NPIX];
__device__ float g_part[IMGS * RED_CTAS * 4];

__device__ __forceinline__ float4 f4min(float4 a, float4 b) {
    return make_float4(fminf(a.x, b.x), fminf(a.y, b.y), fminf(a.z, b.z), fminf(a.w, b.w));
}
__device__ __forceinline__ float4 f4max(float4 a, float4 b) {
    return make_float4(fmaxf(a.x, b.x), fmaxf(a.y, b.y), fmaxf(a.z, b.z), fmaxf(a.w, b.w));
}

// horizontal 3-window min/max across the 128-wide row (one warp = one row).
// lane-edge clamp (shfl returns own value) only corrupts the invalid ring.
__device__ __forceinline__ float4 hmin3(float4 b) {
    float lw = __shfl_up_sync(0xffffffffu, b.w, 1);
    float rx = __shfl_down_sync(0xffffffffu, b.x, 1);
    float4 r;
    r.x = fminf(fminf(lw, b.x), b.y);
    r.y = fminf(fminf(b.x, b.y), b.z);
    r.z = fminf(fminf(b.y, b.z), b.w);
    r.w = fminf(fminf(b.z, b.w), rx);
    return r;
}
__device__ __forceinline__ float4 hmax3(float4 b) {
    float lw = __shfl_up_sync(0xffffffffu, b.w, 1);
    float rx = __shfl_down_sync(0xffffffffu, b.x, 1);
    float4 r;
    r.x = fmaxf(fmaxf(lw, b.x), b.y);
    r.y = fmaxf(fmaxf(b.x, b.y), b.z);
    r.z = fmaxf(fmaxf(b.y, b.z), b.w);
    r.w = fmaxf(fmaxf(b.z, b.w), rx);
    return r;
}

__device__ __forceinline__ float4 selneg(bool m, float4 v) {
    const float NI_F = __int_as_float(0xff800000);
    return m ? make_float4(NI_F, NI_F, NI_F, NI_F) : v;
}

// single boundary smem array: element index [kind(min=0/max=1)][par][warp][tb][lane]
#define BMIN_OFF 0
#define BMAX_OFF 2048
__device__ __forceinline__ int BI(int par, int w, int tb, int lane) {
    return (par << 10) + (w << 6) + (tb << 5) + lane;
}

struct Ctx {
    int w, lane, r0;
    bool outw, xany, yany, xout;
    unsigned rmask;   // bit v = own region row r0+v lies outside the image
};

// one iteration: erode in[] -> out[] (registers; pre-reduced boundaries via
// smem, nothing carried across the sync), then dilate+skel+acc post-sync.
// Image-border masking is applied by the row OWNER at publish time for
// boundary rows and locally (branch-gated) for interior rows.
// PAR = t&1 picks the ping-pong halves.
template <int PAR>
__device__ __forceinline__ void step_it(
    int t, bool dil, const Ctx& cx,
    float4 (&in)[ROWS_PW], float4 (&out)[ROWS_PW],
    float4 (&prod)[ROWS_PW], float4 (&acc)[ROWS_PW],
    float4* bnd)
{
    const int w = cx.w, lane = cx.lane;
    const bool active = (cx.r0 + ROWS_PW - 1 >= t + 1) && (cx.r0 <= 94 - t);

    if (active) {
        // ---- erosion: all boundary rows arrive pre-min'd from smem ----
        float4 hup = bnd[BMIN_OFF + BI(PAR, (w > 0) ? w - 1 : w, (w > 0) ? 1 : 0, lane)];
        float4 hts = bnd[BMIN_OFF + BI(PAR, w, 0, lane)];
        float4 hbs = bnd[BMIN_OFF + BI(PAR, w, 1, lane)];
        float4 hdn = bnd[BMIN_OFF + BI(PAR, (w < WARPS - 1) ? w + 1 : w,
                                            (w < WARPS - 1) ? 0 : 1, lane)];
        float4 h1 = hmin3(in[1]);
        float4 h2 = hmin3(in[2]);
        float4 h3 = hmin3(in[3]);
        float4 h4 = hmin3(in[4]);
        out[0] = f4min(f4min(hup, hts), h1);
        out[1] = f4min(f4min(hts, h1), h2);
        out[2] = f4min(f4min(h1, h2), h3);
        out[3] = f4min(f4min(h2, h3), h4);
        out[4] = f4min(f4min(h3, h4), hbs);
        out[5] = f4min(f4min(h4, hbs), hdn);
        bnd[BMIN_OFF + BI(PAR ^ 1, w, 0, lane)] = hmin3(out[0]);
        bnd[BMIN_OFF + BI(PAR ^ 1, w, 1, lane)] = hmin3(out[ROWS_PW - 1]);
        if (dil) {
            // publish boundary rows pre-maxed AND pre-masked by the owner
            float4 a0 = out[0], a5 = out[ROWS_PW - 1];
            if (cx.xany) { a0 = selneg(cx.xout, a0); a5 = selneg(cx.xout, a5); }
            float4 hx0 = hmax3(a0), hx5 = hmax3(a5);
            if (cx.yany) {
                hx0 = selneg((cx.rmask >> 0) & 1u, hx0);
                hx5 = selneg((cx.rmask >> 5) & 1u, hx5);
            }
            bnd[BMAX_OFF + BI(PAR, w, 0, lane)] = hx0;
            bnd[BMAX_OFF + BI(PAR, w, 1, lane)] = hx5;
        }
        if (cx.outw) {
#pragma unroll
            for (int v = 0; v < ROWS_PW; ++v) {
                acc[v].x += out[v].x; acc[v].y += out[v].y;
                acc[v].z += out[v].z; acc[v].w += out[v].w;
            }
        }
    }
    __syncthreads();
    if (dil && cx.outw) {
        // dilation of E_{t+1}: interior rows maxed locally (branch-gated
        // masking), 4 boundary rows read back pre-maxed+pre-masked from smem
        float4 mU = bnd[BMAX_OFF + BI(PAR, w - 1, 1, lane)];
        float4 m0 = bnd[BMAX_OFF + BI(PAR, w, 0, lane)];
        float4 m5 = bnd[BMAX_OFF + BI(PAR, w, 1, lane)];
        float4 mD = bnd[BMAX_OFF + BI(PAR, w + 1, 0, lane)];
        float4 i1 = out[1], i2 = out[2], i3 = out[3], i4 = out[4];
        if (cx.xany) {
            i1 = selneg(cx.xout, i1); i2 = selneg(cx.xout, i2);
            i3 = selneg(cx.xout, i3); i4 = selneg(cx.xout, i4);
        }
        float4 m1 = hmax3(i1);
        float4 m2 = hmax3(i2);
        float4 m3 = hmax3(i3);
        float4 m4 = hmax3(i4);
        if (cx.yany) {
            m1 = selneg((cx.rmask >> 1) & 1u, m1);
            m2 = selneg((cx.rmask >> 2) & 1u, m2);
            m3 = selneg((cx.rmask >> 3) & 1u, m3);
            m4 = selneg((cx.rmask >> 4) & 1u, m4);
        }
#define DROW(v, a, b, c) { \
        float4 d = f4max(f4max(a, b), c); \
        prod[v].x = fmaf(prod[v].x, d.x - in[v].x, prod[v].x); \
        prod[v].y = fmaf(prod[v].y, d.y - in[v].y, prod[v].y); \
        prod[v].z = fmaf(prod[v].z, d.z - in[v].z, prod[v].z); \
        prod[v].w = fmaf(prod[v].w, d.w - in[v].w, prod[v].w); }
        DROW(0, mU, m0, m1)
        DROW(1, m0, m1, m2)
        DROW(2, m1, m2, m3)
        DROW(3, m2, m3, m4)
        DROW(4, m3, m4, m5)
        DROW(5, m4, m5, mD)
#undef DROW
    }
}

// Fused morphology: each warp keeps a 6-row strip of the erosion state in
// registers; smem carries only pre-reduced boundary rows (ping-pong).
// grid = (8, 12, 64): z = img*2 + which (0 = pred, 1 = target)
__global__ __launch_bounds__(THREADS, 1)
void morph_kernel(const float* __restrict__ P, const float* __restrict__ Gt) {
    const int tz = blockIdx.z;
    const int img = tz >> 1;
    const int which = tz & 1;
    const float* __restrict__ src = (which ? Gt : P) + img * NPIX;

    const int tx0 = blockIdx.x * TW;
    const int ty0 = blockIdx.y * TH;
    const int tid = threadIdx.x;
    const int lane = tid & 31;
    const int w = tid >> 5;
    const int r0 = ROWS_PW * w;
    const int gx0 = tx0 - 16 + 4 * lane;

    extern __shared__ float4 bnd[];   // [min/max][2][16][2][32] float4 = 64 KB

    const float PI_F = __int_as_float(0x7f800000);   // +inf

    float4 cur[ROWS_PW], nxt[ROWS_PW], prod[ROWS_PW], acc[ROWS_PW];

    // ---- load E_0 strip: rows ty0-16+r0+v, cols gx0..gx0+3; +inf outside ----
#pragma unroll
    for (int v = 0; v < ROWS_PW; ++v) {
        int gy = ty0 - 16 + r0 + v;
        float4 val = make_float4(PI_F, PI_F, PI_F, PI_F);
        if ((unsigned)gy < (unsigned)H && (unsigned)gx0 < (unsigned)W)
            val = *(const float4*)(src + gy * W + gx0);
        cur[v] = val;
        prod[v] = make_float4(1.f, 1.f, 1.f, 1.f);
        acc[v] = make_float4(0.f, 0.f, 0.f, 0.f);
    }
    bnd[BMIN_OFF + BI(0, w, 0, lane)] = hmin3(cur[0]);
    bnd[BMIN_OFF + BI(0, w, 1, lane)] = hmin3(cur[ROWS_PW - 1]);
    __syncthreads();

    Ctx cx;
    cx.w = w; cx.lane = lane; cx.r0 = r0;
    cx.outw = (w >= 2 && w <= 13);   // strips overlapping output rows 16..79
    cx.xany = (tx0 == 0) || (tx0 + TW == W);
    const bool t0 = (ty0 == 0), b0 = (ty0 + TH == H);
    cx.yany = t0 || b0;
    cx.xout = (tx0 == 0 && lane < 4) || (tx0 + TW == W && lane >= 28);
    cx.rmask = 0u;
#pragma unroll
    for (int v = 0; v < ROWS_PW; ++v) {
        int r = r0 + v;
        if ((t0 && r < 16) || (b0 && r > 79)) cx.rmask |= (1u << v);
    }

#pragma unroll 1
    for (int t = 0; t < 16; t += 2) {
        step_it<0>(t,     t     <= 10, cx, cur, nxt, prod, acc, bnd);
        step_it<1>(t + 1, t + 1 <= 10, cx, nxt, cur, prod, acc, bnd);
    }

    // ---- write outputs: region rows 16..79, cols = lanes 4..27 ----
    if (cx.outw && lane >= 4 && lane < 28) {
        float* skelp = g_skel[which] + img * NPIX;
        float* accp  = g_acc[which] + img * NPIX;
        const int gxo = tx0 + 4 * (lane - 4);
#pragma unroll
        for (int v = 0; v < ROWS_PW; ++v) {
            const int r = r0 + v;
            if (r >= 16 && r < 80) {
                const int off = (ty0 + r - 16) * W + gxo;
                float4 s = make_float4(1.f - prod[v].x, 1.f - prod[v].y,
                                       1.f - prod[v].z, 1.f - prod[v].w);
                *(float4*)(skelp + off) = s;
                *(float4*)(accp + off) = acc[v];
            }
        }
    }
}

// Per-image partial sums: a1 = sum(S_P*G*r_G), a2 = sum(S_P*r_G),
//                         b1 = sum(S_G*P*r_P), b2 = sum(S_G*r_P)
__global__ __launch_bounds__(RED_THREADS)
void reduce_kernel(const float* __restrict__ P, const float* __restrict__ G) {
    const int img = blockIdx.y;
    const int base = img * NPIX + blockIdx.x * (NPIX / RED_CTAS);
    const float inv16 = 1.0f / 16.0f;
    float a1 = 0.f, a2 = 0.f, b1 = 0.f, b2 = 0.f;
#pragma unroll
    for (int it = 0; it < 9; ++it) {
        int off = base + (it * RED_THREADS + threadIdx.x) * 4;
        float4 sp = *(const float4*)(&g_skel[0][off]);
        float4 sg = *(const float4*)(&g_skel[1][off]);
        float4 ap = *(const float4*)(&g_acc[0][off]);
        float4 ag = *(const float4*)(&g_acc[1][off]);
        float4 pv = *(const float4*)(&P[off]);
        float4 gv = *(const float4*)(&G[off]);
#define ACCUM(c) { \
        float rg = ag.c * inv16 * gv.c + EPS; \
        float rp = ap.c * inv16 * pv.c + EPS; \
        a1 += sp.c * gv.c * rg; a2 += sp.c * rg; \
        b1 += sg.c * pv.c * rp; b2 += sg.c * rp; }
        ACCUM(x) ACCUM(y) ACCUM(z) ACCUM(w)
#undef ACCUM
    }
#pragma unroll
    for (int o = 16; o; o >>= 1) {
        a1 += __shfl_down_sync(0xffffffffu, a1, o);
        a2 += __shfl_down_sync(0xffffffffu, a2, o);
        b1 += __shfl_down_sync(0xffffffffu, b1, o);
        b2 += __shfl_down_sync(0xffffffffu, b2, o);
    }
    __shared__ float sm[8][4];
    const int lane = threadIdx.x & 31, wrp = threadIdx.x >> 5;
    if (lane == 0) { sm[wrp][0] = a1; sm[wrp][1] = a2; sm[wrp][2] = b1; sm[wrp][3] = b2; }
    __syncthreads();
    if (threadIdx.x < 4) {
        float s = 0.f;
#pragma unroll
        for (int ww = 0; ww < 8; ++ww) s += sm[ww][threadIdx.x];
        g_part[(img * RED_CTAS + blockIdx.x) * 4 + threadIdx.x] = s;
    }
}

__global__ void final_kernel(float* __restrict__ out) {
    __shared__ float sums[IMGS][4];
    const int tid = threadIdx.x;
    if (tid < IMGS * 4) {
        int img = tid >> 2, k = tid & 3;
        float s = 0.f;
        for (int c = 0; c < RED_CTAS; ++c)
            s += g_part[(img * RED_CTAS + c) * 4 + k];
        sums[img][k] = s;
    }
    __syncthreads();
    if (tid == 0) {
        float loss = 0.f;
        for (int i = 0; i < IMGS; ++i) {
            float prec = sums[i][0] / (sums[i][1] + EPS);
            float rec  = sums[i][2] / (sums[i][3] + EPS);
            float cbd  = 2.f * prec * rec / (prec + rec + EPS);
            loss += 1.f - cbd;
        }
        out[0] = loss / (float)IMGS;
    }
}

extern "C" void kernel_launch(void* const* d_in, const int* in_sizes, int n_in,
                              void* d_out, int out_size) {
    const float* P = (const float*)d_in[0];   // pred
    const float* G = (const float*)d_in[1];   // target
    const size_t smem_bytes = 4096u * sizeof(float4);  // 65536 (dynamic)
    cudaFuncSetAttribute(morph_kernel, cudaFuncAttributeMaxDynamicSharedMemorySize,
                         (int)smem_bytes);
    dim3 grid(W / TW, H / TH, IMGS * 2);
    morph_kernel<<<grid, THREADS, smem_bytes>>>(P, G);
    reduce_kernel<<<dim3(RED_CTAS, IMGS), RED_THREADS>>>(P, G);
    final_kernel<<<1, 128>>>((float*)d_out);
}

// round 13
// speedup vs baseline: 1.1767x; 1.1767x over previous
#include <cuda_runtime.h>
#include <cstdint>

#define IMGS 32
#define H 768
#define W 768
#define NPIX (H*W)
#define TW 96            // output tile width
#define TH 64            // output tile height
#define WARPS 16
#define THREADS (WARPS*32)
#define ROWS_PW 6        // region rows per warp
#define EPS 1e-6f
#define RED_CTAS 64
#define RED_THREADS 256

__device__ float g_skel[2][IMGS * NPIX];
__device__ float g_acc[2][IMGS * NPIX];
__device__ float g_part[IMGS * RED_CTAS * 4];

__device__ __forceinline__ float4 f4min(float4 a, float4 b) {
    return make_float4(fminf(a.x, b.x), fminf(a.y, b.y), fminf(a.z, b.z), fminf(a.w, b.w));
}
__device__ __forceinline__ float4 f4max(float4 a, float4 b) {
    return make_float4(fmaxf(a.x, b.x), fmaxf(a.y, b.y), fmaxf(a.z, b.z), fmaxf(a.w, b.w));
}

// horizontal 3-window min/max across the 128-wide row (one warp = one row).
// lane-edge clamp (shfl returns own value) only corrupts the invalid ring.
__device__ __forceinline__ float4 hmin3(float4 b) {
    float lw = __shfl_up_sync(0xffffffffu, b.w, 1);
    float rx = __shfl_down_sync(0xffffffffu, b.x, 1);
    float4 r;
    r.x = fminf(fminf(lw, b.x), b.y);
    r.y = fminf(fminf(b.x, b.y), b.z);
    r.z = fminf(fminf(b.y, b.z), b.w);
    r.w = fminf(fminf(b.z, b.w), rx);
    return r;
}
__device__ __forceinline__ float4 hmax3(float4 b) {
    float lw = __shfl_up_sync(0xffffffffu, b.w, 1);
    float rx = __shfl_down_sync(0xffffffffu, b.x, 1);
    float4 r;
    r.x = fmaxf(fmaxf(lw, b.x), b.y);
    r.y = fmaxf(fmaxf(b.x, b.y), b.z);
    r.z = fmaxf(fmaxf(b.y, b.z), b.w);
    r.w = fmaxf(fmaxf(b.z, b.w), rx);
    return r;
}

__device__ __forceinline__ float4 selneg(bool m, float4 v) {
    const float NI_F = __int_as_float(0xff800000);
    return m ? make_float4(NI_F, NI_F, NI_F, NI_F) : v;
}

// boundary smem element index: [kind(min=0/max=1)*2048] + [par][warp][tb][lane]
#define BMIN_OFF 0
#define BMAX_OFF 2048
__device__ __forceinline__ int BI(int par, int w, int tb, int lane) {
    return (par << 10) + (w << 6) + (tb << 5) + lane;
}

struct Ctx {
    int w, lane, r0;
    bool outw, xany, yany, xout;
    unsigned rmask;   // bit v = own region row r0+v lies outside the image
};

// one iteration: erode in[] -> out[] with a ROLLING 3-wide vertical window
// (pre-reduced boundaries via smem; nothing carried across the sync), then
// dilate+skel+acc post-sync, also rolled. PAR = t&1 picks ping-pong halves.
template <int PAR>
__device__ __forceinline__ void step_it(
    int t, bool dil, const Ctx& cx,
    float4 (&in)[ROWS_PW], float4 (&out)[ROWS_PW],
    float4 (&prod)[ROWS_PW], float4 (&acc)[ROWS_PW],
    float4* bnd)
{
    const int w = cx.w, lane = cx.lane;
    const bool active = (cx.r0 + ROWS_PW - 1 >= t + 1) && (cx.r0 <= 94 - t);

    if (active) {
        // ---- erosion, rolled: h-window = hp,hc,hn; boundary h's from smem ----
        float4 hp = bnd[BMIN_OFF + BI(PAR, (w > 0) ? w - 1 : w, (w > 0) ? 1 : 0, lane)];
        float4 hc = bnd[BMIN_OFF + BI(PAR, w, 0, lane)];
#pragma unroll
        for (int v = 0; v < ROWS_PW; ++v) {
            float4 hn;
            if (v < ROWS_PW - 2)      hn = hmin3(in[v + 1]);
            else if (v == ROWS_PW - 2) hn = bnd[BMIN_OFF + BI(PAR, w, 1, lane)];
            else                       hn = bnd[BMIN_OFF + BI(PAR, (w < WARPS - 1) ? w + 1 : w,
                                                                   (w < WARPS - 1) ? 0 : 1, lane)];
            out[v] = f4min(f4min(hp, hc), hn);
            if (cx.outw) {
                acc[v].x += out[v].x; acc[v].y += out[v].y;
                acc[v].z += out[v].z; acc[v].w += out[v].w;
            }
            hp = hc; hc = hn;
        }
        bnd[BMIN_OFF + BI(PAR ^ 1, w, 0, lane)] = hmin3(out[0]);
        bnd[BMIN_OFF + BI(PAR ^ 1, w, 1, lane)] = hmin3(out[ROWS_PW - 1]);
        if (dil) {
            // publish boundary rows pre-maxed AND pre-masked by the owner
            float4 a0 = out[0], a5 = out[ROWS_PW - 1];
            if (cx.xany) { a0 = selneg(cx.xout, a0); a5 = selneg(cx.xout, a5); }
            float4 hx0 = hmax3(a0), hx5 = hmax3(a5);
            if (cx.yany) {
                hx0 = selneg((cx.rmask >> 0) & 1u, hx0);
                hx5 = selneg((cx.rmask >> (ROWS_PW - 1)) & 1u, hx5);
            }
            bnd[BMAX_OFF + BI(PAR, w, 0, lane)] = hx0;
            bnd[BMAX_OFF + BI(PAR, w, 1, lane)] = hx5;
        }
    }
    __syncthreads();
    if (dil && cx.outw) {
        // ---- dilation, rolled: m-window = ma,mb,mc; boundary m's from smem
        //      arrive pre-maxed+pre-masked ----
        float4 ma = bnd[BMAX_OFF + BI(PAR, w - 1, 1, lane)];
        float4 mb = bnd[BMAX_OFF + BI(PAR, w, 0, lane)];
#pragma unroll
        for (int v = 0; v < ROWS_PW; ++v) {
            float4 mc;
            if (v < ROWS_PW - 2) {
                float4 iv = out[v + 1];
                if (cx.xany) iv = selneg(cx.xout, iv);
                mc = hmax3(iv);
                if (cx.yany) mc = selneg((cx.rmask >> (v + 1)) & 1u, mc);
            } else if (v == ROWS_PW - 2) {
                mc = bnd[BMAX_OFF + BI(PAR, w, 1, lane)];
            } else {
                mc = bnd[BMAX_OFF + BI(PAR, w + 1, 0, lane)];
            }
            float4 d = f4max(f4max(ma, mb), mc);
            prod[v].x = fmaf(prod[v].x, d.x - in[v].x, prod[v].x);
            prod[v].y = fmaf(prod[v].y, d.y - in[v].y, prod[v].y);
            prod[v].z = fmaf(prod[v].z, d.z - in[v].z, prod[v].z);
            prod[v].w = fmaf(prod[v].w, d.w - in[v].w, prod[v].w);
            ma = mb; mb = mc;
        }
    }
}

// Fused morphology: each warp keeps a 6-row strip of the erosion state in
// registers; smem carries only pre-reduced boundary rows (ping-pong).
// grid = (8, 12, 64): z = img*2 + which (0 = pred, 1 = target)
__global__ __launch_bounds__(THREADS, 1)
void morph_kernel(const float* __restrict__ P, const float* __restrict__ Gt) {
    const int tz = blockIdx.z;
    const int img = tz >> 1;
    const int which = tz & 1;
    const float* __restrict__ src = (which ? Gt : P) + img * NPIX;

    const int tx0 = blockIdx.x * TW;
    const int ty0 = blockIdx.y * TH;
    const int tid = threadIdx.x;
    const int lane = tid & 31;
    const int w = tid >> 5;
    const int r0 = ROWS_PW * w;
    const int gx0 = tx0 - 16 + 4 * lane;

    extern __shared__ float4 bnd[];   // [min/max][2][16][2][32] float4 = 64 KB

    const float PI_F = __int_as_float(0x7f800000);   // +inf

    float4 cur[ROWS_PW], nxt[ROWS_PW], prod[ROWS_PW], acc[ROWS_PW];

    // ---- load E_0 strip: rows ty0-16+r0+v, cols gx0..gx0+3; +inf outside ----
#pragma unroll
    for (int v = 0; v < ROWS_PW; ++v) {
        int gy = ty0 - 16 + r0 + v;
        float4 val = make_float4(PI_F, PI_F, PI_F, PI_F);
        if ((unsigned)gy < (unsigned)H && (unsigned)gx0 < (unsigned)W)
            val = *(const float4*)(src + gy * W + gx0);
        cur[v] = val;
        prod[v] = make_float4(1.f, 1.f, 1.f, 1.f);
        acc[v] = make_float4(0.f, 0.f, 0.f, 0.f);
    }
    bnd[BMIN_OFF + BI(0, w, 0, lane)] = hmin3(cur[0]);
    bnd[BMIN_OFF + BI(0, w, 1, lane)] = hmin3(cur[ROWS_PW - 1]);
    __syncthreads();

    Ctx cx;
    cx.w = w; cx.lane = lane; cx.r0 = r0;
    cx.outw = (w >= 2 && w <= 13);   // strips overlapping output rows 16..79
    cx.xany = (tx0 == 0) || (tx0 + TW == W);
    const bool t0 = (ty0 == 0), b0 = (ty0 + TH == H);
    cx.yany = t0 || b0;
    cx.xout = (tx0 == 0 && lane < 4) || (tx0 + TW == W && lane >= 28);
    cx.rmask = 0u;
#pragma unroll
    for (int v = 0; v < ROWS_PW; ++v) {
        int r = r0 + v;
        if ((t0 && r < 16) || (b0 && r > 79)) cx.rmask |= (1u << v);
    }

#pragma unroll 1
    for (int t = 0; t < 16; t += 2) {
        step_it<0>(t,     t     <= 10, cx, cur, nxt, prod, acc, bnd);
        step_it<1>(t + 1, t + 1 <= 10, cx, nxt, cur, prod, acc, bnd);
    }

    // ---- write outputs: region rows 16..79, cols = lanes 4..27 ----
    if (cx.outw && lane >= 4 && lane < 28) {
        float* skelp = g_skel[which] + img * NPIX;
        float* accp  = g_acc[which] + img * NPIX;
        const int gxo = tx0 + 4 * (lane - 4);
#pragma unroll
        for (int v = 0; v < ROWS_PW; ++v) {
            const int r = r0 + v;
            if (r >= 16 && r < 80) {
                const int off = (ty0 + r - 16) * W + gxo;
                float4 s = make_float4(1.f - prod[v].x, 1.f - prod[v].y,
                                       1.f - prod[v].z, 1.f - prod[v].w);
                *(float4*)(skelp + off) = s;
                *(float4*)(accp + off) = acc[v];
            }
        }
    }
}

// Per-image partial sums: a1 = sum(S_P*G*r_G), a2 = sum(S_P*r_G),
//                         b1 = sum(S_G*P*r_P), b2 = sum(S_G*r_P)
__global__ __launch_bounds__(RED_THREADS)
void reduce_kernel(const float* __restrict__ P, const float* __restrict__ G) {
    const int img = blockIdx.y;
    const int base = img * NPIX + blockIdx.x * (NPIX / RED_CTAS);
    const float inv16 = 1.0f / 16.0f;
    float a1 = 0.f, a2 = 0.f, b1 = 0.f, b2 = 0.f;
#pragma unroll
    for (int it = 0; it < 9; ++it) {
        int off = base + (it * RED_THREADS + threadIdx.x) * 4;
        float4 sp = *(const float4*)(&g_skel[0][off]);
        float4 sg = *(const float4*)(&g_skel[1][off]);
        float4 ap = *(const float4*)(&g_acc[0][off]);
        float4 ag = *(const float4*)(&g_acc[1][off]);
        float4 pv = *(const float4*)(&P[off]);
        float4 gv = *(const float4*)(&G[off]);
#define ACCUM(c) { \
        float rg = ag.c * inv16 * gv.c + EPS; \
        float rp = ap.c * inv16 * pv.c + EPS; \
        a1 += sp.c * gv.c * rg; a2 += sp.c * rg; \
        b1 += sg.c * pv.c * rp; b2 += sg.c * rp; }
        ACCUM(x) ACCUM(y) ACCUM(z) ACCUM(w)
#undef ACCUM
    }
#pragma unroll
    for (int o = 16; o; o >>= 1) {
        a1 += __shfl_down_sync(0xffffffffu, a1, o);
        a2 += __shfl_down_sync(0xffffffffu, a2, o);
        b1 += __shfl_down_sync(0xffffffffu, b1, o);
        b2 += __shfl_down_sync(0xffffffffu, b2, o);
    }
    __shared__ float sm[8][4];
    const int lane = threadIdx.x & 31, wrp = threadIdx.x >> 5;
    if (lane == 0) { sm[wrp][0] = a1; sm[wrp][1] = a2; sm[wrp][2] = b1; sm[wrp][3] = b2; }
    __syncthreads();
    if (threadIdx.x < 4) {
        float s = 0.f;
#pragma unroll
        for (int ww = 0; ww < 8; ++ww) s += sm[ww][threadIdx.x];
        g_part[(img * RED_CTAS + blockIdx.x) * 4 + threadIdx.x] = s;
    }
}

__global__ void final_kernel(float* __restrict__ out) {
    __shared__ float sums[IMGS][4];
    const int tid = threadIdx.x;
    if (tid < IMGS * 4) {
        int img = tid >> 2, k = tid & 3;
        float s = 0.f;
        for (int c = 0; c < RED_CTAS; ++c)
            s += g_part[(img * RED_CTAS + c) * 4 + k];
        sums[img][k] = s;
    }
    __syncthreads();
    if (tid == 0) {
        float loss = 0.f;
        for (int i = 0; i < IMGS; ++i) {
            float prec = sums[i][0] / (sums[i][1] + EPS);
            float rec  = sums[i][2] / (sums[i][3] + EPS);
            float cbd  = 2.f * prec * rec / (prec + rec + EPS);
            loss += 1.f - cbd;
        }
        out[0] = loss / (float)IMGS;
    }
}

extern "C" void kernel_launch(void* const* d_in, const int* in_sizes, int n_in,
                              void* d_out, int out_size) {
    const float* P = (const float*)d_in[0];   // pred
    const float* G = (const float*)d_in[1];   // target
    const size_t smem_bytes = 4096u * sizeof(float4);  // 65536 (dynamic)
    cudaFuncSetAttribute(morph_kernel, cudaFuncAttributeMaxDynamicSharedMemorySize,
                         (int)smem_bytes);
    dim3 grid(W / TW, H / TH, IMGS * 2);
    morph_kernel<<<grid, THREADS, smem_bytes>>>(P, G);
    reduce_kernel<<<dim3(RED_CTAS, IMGS), RED_THREADS>>>(P, G);
    final_kernel<<<1, 128>>>((float*)d_out);
}